// round 6
// baseline (speedup 1.0000x reference)
#include <cuda_runtime.h>
#include <cstdint>

// Problem constants
#define T_STEPS 16384
#define HID     2048
#define IN_SZ   512
#define OUT_SZ  512
#define WH_LD   2560      // HID + IN_SZ
#define NBLK    128       // CTAs in recurrence kernel
#define RPB     16        // rows of h per CTA (NBLK*RPB == HID)

// ---------------------------------------------------------------------------
// Scratch (device globals — no allocation allowed)
// ---------------------------------------------------------------------------
__device__ float  g_pre[(size_t)T_STEPS * HID];   // 128 MB: Wx@x_t + bh
__device__ float  g_H  [(size_t)T_STEPS * HID];   // 128 MB: h_t for output GEMM
__device__ float4 g_hbuf[2][HID / 2];             // (val,tag) pairs, 16B-aligned

// ---------------------------------------------------------------------------
// PTX helpers
// ---------------------------------------------------------------------------
__device__ __forceinline__ float4 ldcg4(const float4* p) {
    float4 v;
    asm volatile("ld.global.cg.v4.f32 {%0,%1,%2,%3},[%4];"
                 : "=f"(v.x), "=f"(v.y), "=f"(v.z), "=f"(v.w) : "l"(p));
    return v;
}
__device__ __forceinline__ void stcg2(float2* p, float a, float b) {
    asm volatile("st.global.cg.v2.f32 [%0],{%1,%2};"
                 :: "l"(p), "f"(a), "f"(b) : "memory");
}
// packed fp32x2 ops (Blackwell); 64-bit register pairs
__device__ __forceinline__ unsigned long long pack2(float lo, float hi) {
    unsigned long long r;
    asm("mov.b64 %0,{%1,%2};" : "=l"(r) : "f"(lo), "f"(hi));
    return r;
}
__device__ __forceinline__ void unpack2(unsigned long long v, float& lo, float& hi) {
    asm("mov.b64 {%0,%1},%2;" : "=f"(lo), "=f"(hi) : "l"(v));
}
__device__ __forceinline__ unsigned long long mul2(unsigned long long a, unsigned long long b) {
    unsigned long long d;
    asm("mul.rn.f32x2 %0,%1,%2;" : "=l"(d) : "l"(a), "l"(b));
    return d;
}
__device__ __forceinline__ unsigned long long fma2(unsigned long long a, unsigned long long b,
                                                   unsigned long long c) {
    unsigned long long d;
    asm("fma.rn.f32x2 %0,%1,%2,%3;" : "=l"(d) : "l"(a), "l"(b), "l"(c));
    return d;
}

// ---------------------------------------------------------------------------
// Init: seed h_0 (tag 0) into buf0, invalidate buf1. Runs every launch.
// ---------------------------------------------------------------------------
__global__ void init_kernel(const float* __restrict__ h0) {
    int i = blockIdx.x * blockDim.x + threadIdx.x;
    if (i < HID) {
        float2* b0 = (float2*)&g_hbuf[0][0];
        float2* b1 = (float2*)&g_hbuf[1][0];
        b0[i] = make_float2(h0[i], __int_as_float(0));
        b1[i] = make_float2(0.f,   __int_as_float(-1));
    }
}

// ---------------------------------------------------------------------------
// Generic fp32 SGEMM with bias:  C[m][n] = bias[n] + sum_k A[m][k]*B[n][k]
// BM=BN=128, BK=8, 256 threads, 8x8 per thread.
// ---------------------------------------------------------------------------
__global__ __launch_bounds__(256) void sgemm_bias(
    const float* __restrict__ A, int lda,
    const float* __restrict__ B, int ldb,
    const float* __restrict__ bias,
    float* __restrict__ C, int ldc, int K)
{
    __shared__ float As[8][128];
    __shared__ float Bs[8][128];
    const int tid  = threadIdx.x;
    const size_t m0 = (size_t)blockIdx.y * 128;
    const int n0   = blockIdx.x * 128;
    const int lrow = tid >> 1;
    const int lc4  = (tid & 1) * 4;
    const int tx   = tid & 15, ty = tid >> 4;

    const float* Ap = A + (m0 + lrow) * (size_t)lda + lc4;
    const float* Bp = B + ((size_t)(n0 + lrow)) * (size_t)ldb + lc4;

    float acc[8][8];
    #pragma unroll
    for (int i = 0; i < 8; i++)
        #pragma unroll
        for (int j = 0; j < 8; j++) acc[i][j] = 0.f;

    for (int k0 = 0; k0 < K; k0 += 8) {
        float4 a4 = *(const float4*)(Ap + k0);
        float4 b4 = *(const float4*)(Bp + k0);
        __syncthreads();
        As[lc4+0][lrow] = a4.x; As[lc4+1][lrow] = a4.y;
        As[lc4+2][lrow] = a4.z; As[lc4+3][lrow] = a4.w;
        Bs[lc4+0][lrow] = b4.x; Bs[lc4+1][lrow] = b4.y;
        Bs[lc4+2][lrow] = b4.z; Bs[lc4+3][lrow] = b4.w;
        __syncthreads();
        #pragma unroll
        for (int kk = 0; kk < 8; kk++) {
            float ar[8], br[8];
            *(float4*)&ar[0] = *(const float4*)&As[kk][ty*8];
            *(float4*)&ar[4] = *(const float4*)&As[kk][ty*8+4];
            *(float4*)&br[0] = *(const float4*)&Bs[kk][tx*8];
            *(float4*)&br[4] = *(const float4*)&Bs[kk][tx*8+4];
            #pragma unroll
            for (int i = 0; i < 8; i++)
                #pragma unroll
                for (int j = 0; j < 8; j++)
                    acc[i][j] = fmaf(ar[i], br[j], acc[i][j]);
        }
    }

    float bv[8];
    *(float4*)&bv[0] = *(const float4*)&bias[n0 + tx*8];
    *(float4*)&bv[4] = *(const float4*)&bias[n0 + tx*8 + 4];
    #pragma unroll
    for (int i = 0; i < 8; i++) {
        size_t crow = m0 + ty*8 + i;
        float4 o0 = make_float4(acc[i][0]+bv[0], acc[i][1]+bv[1],
                                acc[i][2]+bv[2], acc[i][3]+bv[3]);
        float4 o1 = make_float4(acc[i][4]+bv[4], acc[i][5]+bv[5],
                                acc[i][6]+bv[6], acc[i][7]+bv[7]);
        *(float4*)&C[crow * (size_t)ldc + n0 + tx*8]     = o0;
        *(float4*)&C[crow * (size_t)ldc + n0 + tx*8 + 4] = o1;
    }
}

// ---------------------------------------------------------------------------
// Persistent recurrence kernel. 128 CTAs x 512 threads, all co-resident.
// CTA b owns h-rows [16b,16b+16). Whh slice in registers (f32x2 row-pairs).
// Warp w covers columns [128w,128w+128); lane l: c0 = 128w+4l .. c0+3.
// Sync: data-flow only. Producers publish (h, tag=t) as one atomic STG.64
// to L2 (st.cg); consumers poll their own 4 pairs with ld.cg (L2 hits),
// with nanosleep backoff after the first miss (proven stable in R4).
// One hop producer->consumer; no counter, no fence, no consumer barrier.
// ---------------------------------------------------------------------------
__global__ __launch_bounds__(512, 1) void rnn_kernel(const float* __restrict__ Wh)
{
    const int tid  = threadIdx.x;
    const int w    = tid >> 5;
    const int l    = tid & 31;
    const int row0 = blockIdx.x * RPB;
    const int c0   = w * 128 + l * 4;

    // Load + pack this lane's Whh slice (hidden cols 512..2559)
    unsigned long long wp[8][4];
    #pragma unroll
    for (int p = 0; p < 8; p++) {
        float4 a = *(const float4*)&Wh[(size_t)(row0 + 2*p    ) * WH_LD + IN_SZ + c0];
        float4 b = *(const float4*)&Wh[(size_t)(row0 + 2*p + 1) * WH_LD + IN_SZ + c0];
        wp[p][0] = pack2(a.x, b.x);
        wp[p][1] = pack2(a.y, b.y);
        wp[p][2] = pack2(a.z, b.z);
        wp[p][3] = pack2(a.w, b.w);
    }

    __shared__ float sred[2][16 * RPB];   // [parity][warp*16 + row]

    const int pairIdx = c0 >> 1;          // float4 index into g_hbuf row

    for (int t = 1; t <= T_STEPS; t++) {
        // Prefetch pre-activation for my rows (independent of h)
        float pre = 0.f;
        if (tid < RPB)
            pre = g_pre[(size_t)(t - 1) * HID + row0 + tid];

        // ---- poll my 4 (value,tag) pairs of h_{t-1} directly from L2 ----
        const float4* src = &g_hbuf[(t - 1) & 1][0];
        const int tag = t - 1;
        float4 p0, p1;
        bool r0 = false, r1 = false;
        while (true) {
            if (!r0) {
                p0 = ldcg4(src + pairIdx);
                r0 = (__float_as_int(p0.y) == tag) && (__float_as_int(p0.w) == tag);
            }
            if (!r1) {
                p1 = ldcg4(src + pairIdx + 1);
                r1 = (__float_as_int(p1.y) == tag) && (__float_as_int(p1.w) == tag);
            }
            if (r0 && r1) break;
            __nanosleep(16);     // backoff (stability-proven in R4)
        }

        const unsigned long long h0 = pack2(p0.x, p0.x);
        const unsigned long long h1 = pack2(p0.z, p0.z);
        const unsigned long long h2 = pack2(p1.x, p1.x);
        const unsigned long long h3 = pack2(p1.z, p1.z);

        // ---- packed partial dot products: 16 rows (8 pairs) x 4 cols ----
        float v[RPB];
        #pragma unroll
        for (int p = 0; p < 8; p++) {
            unsigned long long acc = mul2(wp[p][0], h0);
            acc = fma2(wp[p][1], h1, acc);
            acc = fma2(wp[p][2], h2, acc);
            acc = fma2(wp[p][3], h3, acc);
            unpack2(acc, v[2*p], v[2*p + 1]);
        }

        // ---- packed butterfly: reduce 16 values across 32 lanes ----
        {
            const bool hi = (l & 16);
            #pragma unroll
            for (int i = 0; i < 8; i++) {
                float keep = hi ? v[i+8] : v[i];
                float send = hi ? v[i]   : v[i+8];
                v[i] = keep + __shfl_xor_sync(0xffffffffu, send, 16);
            }
        }
        {
            const bool hi = (l & 8);
            #pragma unroll
            for (int i = 0; i < 4; i++) {
                float keep = hi ? v[i+4] : v[i];
                float send = hi ? v[i]   : v[i+4];
                v[i] = keep + __shfl_xor_sync(0xffffffffu, send, 8);
            }
        }
        {
            const bool hi = (l & 4);
            #pragma unroll
            for (int i = 0; i < 2; i++) {
                float keep = hi ? v[i+2] : v[i];
                float send = hi ? v[i]   : v[i+2];
                v[i] = keep + __shfl_xor_sync(0xffffffffu, send, 4);
            }
        }
        {
            const bool hi = (l & 2);
            float keep = hi ? v[1] : v[0];
            float send = hi ? v[0] : v[1];
            v[0] = keep + __shfl_xor_sync(0xffffffffu, send, 2);
        }
        v[0] += __shfl_xor_sync(0xffffffffu, v[0], 1);
        // even lane L holds stripe-sum of row (L>>1)&15

        const int par = t & 1;
        if (!(l & 1))
            sred[par][(w << 4) | ((l >> 1) & 15)] = v[0];   // [warp][row]: conflict-free
        __syncthreads();
        // This barrier also certifies: all lanes of this CTA finished READING
        // h_{t-1} before we publish h_t below — which makes parity
        // double-buffering safe against overwrite.

        // ---- final cross-warp reduce + tanh + publish (warp 0, lanes 0..15)
        if (tid < RPB) {
            float s = pre;
            #pragma unroll
            for (int ww = 0; ww < 16; ww++)
                s += sred[par][(ww << 4) | tid];
            float h = tanhf(s);
            g_H[(size_t)(t - 1) * HID + row0 + tid] = h;
            // atomic 8B publish: value + tag in one STG.64 (no fence needed)
            stcg2((float2*)&g_hbuf[par][0] + row0 + tid, h, __int_as_float(t));
        }
        // sred parity double-buffering removes the need for a trailing barrier.
    }
}

// ---------------------------------------------------------------------------
// Launch
// ---------------------------------------------------------------------------
extern "C" void kernel_launch(void* const* d_in, const int* in_sizes, int n_in,
                              void* d_out, int out_size)
{
    const float* x   = (const float*)d_in[0];  // [16384, 512]
    const float* h0  = (const float*)d_in[1];  // [2048]
    const float* Wh  = (const float*)d_in[2];  // [2048, 2560]
    const float* bh  = (const float*)d_in[3];  // [2048]
    const float* Wo  = (const float*)d_in[4];  // [512, 2048]
    const float* bo  = (const float*)d_in[5];  // [512]
    float* out = (float*)d_out;                // [16384, 512]

    float* pre = nullptr;
    float* H   = nullptr;
    cudaGetSymbolAddress((void**)&pre, g_pre);
    cudaGetSymbolAddress((void**)&H,   g_H);

    // Reset tags + seed h_0 (every launch — graph replay safe)
    init_kernel<<<(HID + 255) / 256, 256>>>(h0);

    // PRE = X @ Wx^T + bh   (Wx = Wh[:, :512], row stride 2560)
    sgemm_bias<<<dim3(HID / 128, T_STEPS / 128), 256>>>(
        x, IN_SZ, Wh, WH_LD, bh, pre, HID, IN_SZ);

    // Sequential recurrence (persistent, data-flow synced via (val,tag) pairs)
    rnn_kernel<<<NBLK, 512>>>(Wh);

    // OUT = H @ Wo^T + bo
    sgemm_bias<<<dim3(OUT_SZ / 128, T_STEPS / 128), 256>>>(
        H, HID, Wo, HID, bo, out, OUT_SZ, HID);
}